// round 11
// baseline (speedup 1.0000x reference)
#include <cuda_runtime.h>
#include <cuda_fp16.h>
#include <cstdint>

// Conv 7x7 C=1 implicit GEMM via mma.sync (legacy HMMA; tcgen05 rejected by
// family-level compute_103 target). 2-pass fp16: Ah.B + Al.B, B = RN fp16.
// Tile = 4 rows x 32 px (M=128) x 64 filters, K=64 (k=ky*8+kx).
// 3 CTAs/SM (C overlays A region, regs capped via launch_bounds(256,3)).
// B fragments register-resident; cp.async double-buffered input;
// split-once packed hi|lo staging.

#define HH 224
#define WW 224
#define NB 32
#define NF 64
#define THREADS 256
#define NCTA 444                    // 3 * 148, persistent
#define TY 4
#define TX 32
#define TPI 392                     // 56 * 7 tiles per image
#define NTILES (NB * TPI)           // 12544
#define RAWR 10
#define RAWC 38
#define RAWN (RAWR * RAWC)          // 380

// SMEM layout (bytes). A rows: 72 halves = 144B stride.
// C f32 [64][132] overlays the A region (bytes 0..33792 < 36864).
#define S_AH 0                      // 128 x 144 = 18432
#define S_AL 18432                  // -> 36864
#define S_B  36864                  // 64 x 144 = 9216 -> 46080
#define S_RF 46080                  // raw f32, 2 x 1520 -> 49120
#define S_RHL 49120                 // packed hi|lo u32, 381 -> 50644
#define S_TOT 50656

#define CSTRIDE 132                 // C row stride in f32

__device__ __forceinline__ uint32_t smem_u32(const void* p) {
    uint32_t a;
    asm("{ .reg .u64 t; cvta.to.shared.u64 t, %1; cvt.u32.u64 %0, t; }" : "=r"(a) : "l"(p));
    return a;
}
__device__ __forceinline__ void sts16(uint32_t a, uint32_t v) {
    asm volatile("st.shared.u16 [%0], %1;" :: "r"(a), "r"(v) : "memory");
}
__device__ __forceinline__ void sts32(uint32_t a, uint32_t v) {
    asm volatile("st.shared.b32 [%0], %1;" :: "r"(a), "r"(v) : "memory");
}
__device__ __forceinline__ void sts32f(uint32_t a, float v) {
    asm volatile("st.shared.f32 [%0], %1;" :: "r"(a), "f"(v) : "memory");
}
__device__ __forceinline__ uint32_t lds32(uint32_t a) {
    uint32_t v;
    asm volatile("ld.shared.b32 %0, [%1];" : "=r"(v) : "r"(a));
    return v;
}
__device__ __forceinline__ float lds32f(uint32_t a) {
    float v;
    asm volatile("ld.shared.f32 %0, [%1];" : "=f"(v) : "r"(a));
    return v;
}
__device__ __forceinline__ void sts128(uint32_t a, uint32_t r0, uint32_t r1,
                                       uint32_t r2, uint32_t r3) {
    asm volatile("st.shared.v4.b32 [%0], {%1, %2, %3, %4};"
                 :: "r"(a), "r"(r0), "r"(r1), "r"(r2), "r"(r3) : "memory");
}
__device__ __forceinline__ float4 lds128f(uint32_t a) {
    float4 v;
    asm volatile("ld.shared.v4.f32 {%0, %1, %2, %3}, [%4];"
                 : "=f"(v.x), "=f"(v.y), "=f"(v.z), "=f"(v.w) : "r"(a));
    return v;
}
__device__ __forceinline__ void cpasync4(uint32_t dst, const void* src, uint32_t sz) {
    asm volatile("cp.async.ca.shared.global [%0], [%1], 4, %2;"
                 :: "r"(dst), "l"(src), "r"(sz) : "memory");
}
#define CP_COMMIT() asm volatile("cp.async.commit_group;" ::: "memory")
#define CP_WAIT0()  asm volatile("cp.async.wait_group 0;" ::: "memory")

#define LDSM4(r, addr) \
    asm volatile("ldmatrix.sync.aligned.m8n8.x4.shared.b16 {%0,%1,%2,%3}, [%4];" \
        : "=r"((r)[0]), "=r"((r)[1]), "=r"((r)[2]), "=r"((r)[3]) : "r"(addr))

#define MMA16816(c, a, bb0, bb1) \
    asm volatile("mma.sync.aligned.m16n8k16.row.col.f32.f16.f16.f32 " \
        "{%0,%1,%2,%3}, {%4,%5,%6,%7}, {%8,%9}, {%0,%1,%2,%3};" \
        : "+f"((c)[0]), "+f"((c)[1]), "+f"((c)[2]), "+f"((c)[3]) \
        : "r"((a)[0]), "r"((a)[1]), "r"((a)[2]), "r"((a)[3]), "r"(bb0), "r"(bb1))

__device__ __forceinline__ void split_h(float v, uint32_t& hi, uint32_t& lo) {
    __half h = __float2half(v);
    float r = v - __half2float(h);
    __half l = __float2half(r);
    hi = (uint32_t)__half_as_ushort(h);
    lo = (uint32_t)__half_as_ushort(l);
}

__global__ void __launch_bounds__(THREADS, 3)
conv7x7_mma4_kernel(const float* __restrict__ in,
                    const float* __restrict__ wk,
                    float* __restrict__ out) {
    extern __shared__ char smem[];
    const uint32_t sb = smem_u32(smem);
    const int tid = threadIdx.x;
    const int lane = tid & 31;
    const int wid = tid >> 5;

    // ---- one-time init: zero A + B regions, rawhl overread pad ----
    for (int i = tid * 16; i < S_RF; i += THREADS * 16)
        sts128(sb + i, 0u, 0u, 0u, 0u);
    if (tid == 0) sts32(sb + S_RHL + RAWN * 4, 0u);   // finite pad, kx=7 corner
    __syncthreads();

    // ---- weights -> B fp16 (RN), [f][k=ky*8+kx], row stride 144B ----
    for (int i = tid; i < NF * 49; i += THREADS) {
        int f = i / 49, q = i - f * 49;
        int ky = q / 7, kx = q - ky * 7;
        uint32_t h = (uint32_t)__half_as_ushort(__float2half(wk[i]));
        sts16(sb + S_B + (uint32_t)(f * 144 + (ky * 8 + kx) * 2), h);
    }
    __syncthreads();

    // ---- per-warp ldmatrix lane offsets ----
    const int wm = wid & 3;          // m-tile (4)
    const int wn = wid >> 2;         // n-tile (2)
    const uint32_t aoff = (uint32_t)((wm * 32 + (lane & 15)) * 144 + (lane >> 4) * 16);
    const uint32_t boff = (uint32_t)((wn * 32 + (lane & 7) + ((lane >> 4) & 1) * 8) * 144
                                     + ((lane >> 3) & 1) * 16);

    // ---- B fragments: register-resident for the whole kernel ----
    uint32_t bf[4][8];
    #pragma unroll
    for (int k = 0; k < 4; k++) {
        LDSM4(&bf[k][0], sb + S_B + boff + k * 32);          // n-tiles 0,1
        LDSM4(&bf[k][4], sb + S_B + boff + 2304 + k * 32);   // n-tiles 2,3
    }

    // ---- raw issue helper (cp.async f32, zfill OOB) ----
    auto issue_raw = [&](int tile, int buf) {
        const int b = tile / TPI;
        const int rem = tile - b * TPI;
        const int yp = rem / 7;
        const int xh = rem - yp * 7;
        const int y0 = yp * TY, x0 = xh * TX;
        const float* inb = in + (size_t)b * (HH * WW);
        #pragma unroll
        for (int it = 0; it < 2; it++) {
            int i = tid + it * THREADS;
            if (i < RAWN) {
                int r = i / RAWC, c = i - r * RAWC;
                int gy = y0 - 3 + r, gx = x0 - 3 + c;
                bool ok = (gy >= 0 && gy < HH && gx >= 0 && gx < WW);
                const float* src = ok ? (inb + gy * WW + gx) : inb;
                cpasync4(sb + S_RF + buf * 1520 + (uint32_t)i * 4, src, ok ? 4u : 0u);
            }
        }
    };

    int buf = 0;
    issue_raw(blockIdx.x, 0);
    CP_COMMIT();

    for (int tile = blockIdx.x; tile < NTILES; tile += NCTA) {
        const int b = tile / TPI;
        const int rem = tile - b * TPI;
        const int yp = rem / 7;
        const int xh = rem - yp * 7;
        const int y0 = yp * TY, x0 = xh * TX;

        CP_WAIT0();
        __syncthreads();   // raw[buf] visible; prev tile C reads done

        // ---- phase 1: split raw f32 -> packed (hi | lo<<16) ----
        #pragma unroll
        for (int it = 0; it < 2; it++) {
            int i = tid + it * THREADS;
            if (i < RAWN) {
                float v = lds32f(sb + S_RF + buf * 1520 + (uint32_t)i * 4);
                uint32_t hi, lo;
                split_h(v, hi, lo);
                sts32(sb + S_RHL + (uint32_t)i * 4, hi | (lo << 16));
            }
        }

        // prefetch next tile's raw into other buffer
        {
            int nt = tile + NCTA;
            if (nt < NTILES) issue_raw(nt, buf ^ 1);
            CP_COMMIT();
        }
        __syncthreads();   // rawhl ready

        // ---- phase 2: im2col -> A_hi + A_lo; re-zero cols 56..63 (C overlay) ----
        {
            const int m = tid & 127;          // m = dy*32 + x
            const int half = tid >> 7;
            const int dy = m >> 5, x = m & 31;
            const int ky0 = half ? 4 : 0, ky1 = half ? 7 : 4;
            const uint32_t ah = sb + S_AH + (uint32_t)m * 144;
            const uint32_t al = sb + S_AL + (uint32_t)m * 144;
            for (int ky = ky0; ky < ky1; ky++) {
                uint32_t ra = sb + S_RHL + (uint32_t)(((dy + ky) * RAWC + x) * 4);
                uint32_t w0 = lds32(ra + 0),  w1 = lds32(ra + 4);
                uint32_t w2 = lds32(ra + 8),  w3 = lds32(ra + 12);
                uint32_t w4 = lds32(ra + 16), w5 = lds32(ra + 20);
                uint32_t w6 = lds32(ra + 24), w7 = lds32(ra + 28);
                sts128(ah + ky * 16,
                       __byte_perm(w0, w1, 0x5410), __byte_perm(w2, w3, 0x5410),
                       __byte_perm(w4, w5, 0x5410), __byte_perm(w6, w7, 0x5410));
                sts128(al + ky * 16,
                       __byte_perm(w0, w1, 0x7632), __byte_perm(w2, w3, 0x7632),
                       __byte_perm(w4, w5, 0x7632), __byte_perm(w6, w7, 0x7632));
            }
            // stale C f32 bits live in k 56..63 (B=0 there but must be finite)
            sts128((half ? al : ah) + 112, 0u, 0u, 0u, 0u);
        }
        __syncthreads();   // A ready

        // ---- phase 3: 2-pass warp MMA (B frags resident) ----
        float acc[32];
        #pragma unroll
        for (int i = 0; i < 32; i++) acc[i] = 0.0f;

        #pragma unroll
        for (int p = 0; p < 2; p++) {
            const uint32_t Ab = sb + (p ? S_AL : S_AH) + aoff;
            #pragma unroll
            for (int k = 0; k < 4; k++) {
                uint32_t a0[4], a1[4];
                LDSM4(a0, Ab + k * 32);            // m-tile 0
                LDSM4(a1, Ab + 2304 + k * 32);     // m-tile 1
                MMA16816(acc + 0,  a0, bf[k][0], bf[k][1]);
                MMA16816(acc + 4,  a0, bf[k][2], bf[k][3]);
                MMA16816(acc + 8,  a0, bf[k][4], bf[k][5]);
                MMA16816(acc + 12, a0, bf[k][6], bf[k][7]);
                MMA16816(acc + 16, a1, bf[k][0], bf[k][1]);
                MMA16816(acc + 20, a1, bf[k][2], bf[k][3]);
                MMA16816(acc + 24, a1, bf[k][4], bf[k][5]);
                MMA16816(acc + 28, a1, bf[k][6], bf[k][7]);
            }
        }
        __syncthreads();   // all A reads done before C overlay write

        // ---- phase 4: stage C[n][m] f32 over A region ----
        {
            const int tg = lane & 3, gp = lane >> 2;
            #pragma unroll
            for (int im = 0; im < 2; im++) {
                #pragma unroll
                for (int in_ = 0; in_ < 4; in_++) {
                    const float* a = &acc[(im * 4 + in_) * 4];
                    int n0 = wn * 32 + in_ * 8 + 2 * tg;
                    int m0 = wm * 32 + im * 16 + gp;
                    uint32_t c00 = sb + (uint32_t)((n0 * CSTRIDE + m0) * 4);
                    sts32f(c00, a[0]);
                    sts32f(c00 + CSTRIDE * 4, a[1]);
                    sts32f(c00 + 32, a[2]);
                    sts32f(c00 + CSTRIDE * 4 + 32, a[3]);
                }
            }
        }
        __syncthreads();   // C ready

        // ---- phase 5: coalesced 128B stores, 8 lanes per (f,dy) row ----
        {
            const int p0 = tid >> 3, j = tid & 7;
            #pragma unroll
            for (int it = 0; it < 8; it++) {
                int p = p0 + it * 32;        // (f, dy) pair
                int f = p >> 2, dy = p & 3;
                int m = dy * 32 + j * 4;
                float4 v = lds128f(sb + (uint32_t)((f * CSTRIDE + m) * 4));
                float* po = out + (size_t)b * (NF * HH * WW)
                                + (size_t)f * (HH * WW) + (y0 + dy) * WW + x0;
                *(float4*)(po + j * 4) = v;
            }
        }
        buf ^= 1;
        // loop-top sync orders phase-5 C reads before next tile's A writes
    }
}

extern "C" void kernel_launch(void* const* d_in, const int* in_sizes, int n_in,
                              void* d_out, int out_size) {
    const float* x = (const float*)d_in[0];   // (32,1,224,224) f32
    const float* k = (const float*)d_in[1];   // (64,7,7) f32
    float* out = (float*)d_out;               // (32,64,224,224) f32

    cudaFuncSetAttribute(conv7x7_mma4_kernel,
                         cudaFuncAttributeMaxDynamicSharedMemorySize, S_TOT);
    conv7x7_mma4_kernel<<<NCTA, THREADS, S_TOT>>>(x, k, out);
}

// round 12
// speedup vs baseline: 1.0727x; 1.0727x over previous
#include <cuda_runtime.h>
#include <cuda_fp16.h>
#include <cstdint>

// Conv 7x7 C=1 implicit GEMM via mma.sync (legacy HMMA; tcgen05 rejected by
// family-level compute_103 target). 2-pass fp16: Ah.B + Al.B, B = RN fp16.
// Tile = 4 rows x 32 px (M=128) x 64 filters, K=64 (k=ky*8+kx).
// R12: direct register->gmem epilogue (C SMEM bounce deleted, -64KB/tile
// crossbar traffic, 5->3 barriers/tile), 2 CTAs/SM.
// B fragments register-resident; cp.async double-buffered input;
// split-once packed hi|lo staging.

#define HH 224
#define WW 224
#define HhW (HH * WW)
#define NB 32
#define NF 64
#define THREADS 256
#define NCTA 296                    // 2 * 148, persistent
#define TY 4
#define TX 32
#define TPI 392                     // 56 * 7 tiles per image
#define NTILES (NB * TPI)           // 12544
#define RAWR 10
#define RAWC 38
#define RAWN (RAWR * RAWC)          // 380

// SMEM layout (bytes). A rows: 72 halves = 144B stride.
#define S_AH 0                      // 128 x 144 = 18432
#define S_AL 18432                  // -> 36864
#define S_B  36864                  // 64 x 144 = 9216 -> 46080
#define S_RF 46080                  // raw f32, 2 x 1520 -> 49120
#define S_RHL 49120                 // packed hi|lo u32, 381 -> 50644
#define S_TOT 50656

__device__ __forceinline__ uint32_t smem_u32(const void* p) {
    uint32_t a;
    asm("{ .reg .u64 t; cvta.to.shared.u64 t, %1; cvt.u32.u64 %0, t; }" : "=r"(a) : "l"(p));
    return a;
}
__device__ __forceinline__ void sts16(uint32_t a, uint32_t v) {
    asm volatile("st.shared.u16 [%0], %1;" :: "r"(a), "r"(v) : "memory");
}
__device__ __forceinline__ void sts32(uint32_t a, uint32_t v) {
    asm volatile("st.shared.b32 [%0], %1;" :: "r"(a), "r"(v) : "memory");
}
__device__ __forceinline__ uint32_t lds32(uint32_t a) {
    uint32_t v;
    asm volatile("ld.shared.b32 %0, [%1];" : "=r"(v) : "r"(a));
    return v;
}
__device__ __forceinline__ float lds32f(uint32_t a) {
    float v;
    asm volatile("ld.shared.f32 %0, [%1];" : "=f"(v) : "r"(a));
    return v;
}
__device__ __forceinline__ void sts128(uint32_t a, uint32_t r0, uint32_t r1,
                                       uint32_t r2, uint32_t r3) {
    asm volatile("st.shared.v4.b32 [%0], {%1, %2, %3, %4};"
                 :: "r"(a), "r"(r0), "r"(r1), "r"(r2), "r"(r3) : "memory");
}
__device__ __forceinline__ void cpasync4(uint32_t dst, const void* src, uint32_t sz) {
    asm volatile("cp.async.ca.shared.global [%0], [%1], 4, %2;"
                 :: "r"(dst), "l"(src), "r"(sz) : "memory");
}
#define CP_COMMIT() asm volatile("cp.async.commit_group;" ::: "memory")
#define CP_WAIT0()  asm volatile("cp.async.wait_group 0;" ::: "memory")

#define LDSM4(r, addr) \
    asm volatile("ldmatrix.sync.aligned.m8n8.x4.shared.b16 {%0,%1,%2,%3}, [%4];" \
        : "=r"((r)[0]), "=r"((r)[1]), "=r"((r)[2]), "=r"((r)[3]) : "r"(addr))

#define MMA16816(c, a, bb0, bb1) \
    asm volatile("mma.sync.aligned.m16n8k16.row.col.f32.f16.f16.f32 " \
        "{%0,%1,%2,%3}, {%4,%5,%6,%7}, {%8,%9}, {%0,%1,%2,%3};" \
        : "+f"((c)[0]), "+f"((c)[1]), "+f"((c)[2]), "+f"((c)[3]) \
        : "r"((a)[0]), "r"((a)[1]), "r"((a)[2]), "r"((a)[3]), "r"(bb0), "r"(bb1))

__device__ __forceinline__ void split_h(float v, uint32_t& hi, uint32_t& lo) {
    __half h = __float2half(v);
    float r = v - __half2float(h);
    __half l = __float2half(r);
    hi = (uint32_t)__half_as_ushort(h);
    lo = (uint32_t)__half_as_ushort(l);
}

__global__ void __launch_bounds__(THREADS, 2)
conv7x7_mma5_kernel(const float* __restrict__ in,
                    const float* __restrict__ wk,
                    float* __restrict__ out) {
    extern __shared__ char smem[];
    const uint32_t sb = smem_u32(smem);
    const int tid = threadIdx.x;
    const int lane = tid & 31;
    const int wid = tid >> 5;

    // ---- one-time init: zero A + B regions (padding stays zero forever) ----
    for (int i = tid * 16; i < S_RF; i += THREADS * 16)
        sts128(sb + i, 0u, 0u, 0u, 0u);
    if (tid == 0) sts32(sb + S_RHL + RAWN * 4, 0u);   // finite pad, kx=7 corner
    __syncthreads();

    // ---- weights -> B fp16 (RN), [f][k=ky*8+kx], row stride 144B ----
    for (int i = tid; i < NF * 49; i += THREADS) {
        int f = i / 49, q = i - f * 49;
        int ky = q / 7, kx = q - ky * 7;
        uint32_t h = (uint32_t)__half_as_ushort(__float2half(wk[i]));
        sts16(sb + S_B + (uint32_t)(f * 144 + (ky * 8 + kx) * 2), h);
    }
    __syncthreads();

    // ---- per-warp ldmatrix lane offsets ----
    const int wm = wid & 3;          // m-tile (4) == dy of this warp's pixels
    const int wn = wid >> 2;         // n-tile (2)
    const uint32_t aoff = (uint32_t)((wm * 32 + (lane & 15)) * 144 + (lane >> 4) * 16);
    const uint32_t boff = (uint32_t)((wn * 32 + (lane & 7) + ((lane >> 4) & 1) * 8) * 144
                                     + ((lane >> 3) & 1) * 16);

    // ---- B fragments: register-resident for the whole kernel ----
    uint32_t bf[4][8];
    #pragma unroll
    for (int k = 0; k < 4; k++) {
        LDSM4(&bf[k][0], sb + S_B + boff + k * 32);          // n-tiles 0,1
        LDSM4(&bf[k][4], sb + S_B + boff + 2304 + k * 32);   // n-tiles 2,3
    }

    // ---- raw issue helper (cp.async f32, zfill OOB) ----
    auto issue_raw = [&](int tile, int buf) {
        const int b = tile / TPI;
        const int rem = tile - b * TPI;
        const int yp = rem / 7;
        const int xh = rem - yp * 7;
        const int y0 = yp * TY, x0 = xh * TX;
        const float* inb = in + (size_t)b * HhW;
        #pragma unroll
        for (int it = 0; it < 2; it++) {
            int i = tid + it * THREADS;
            if (i < RAWN) {
                int r = i / RAWC, c = i - r * RAWC;
                int gy = y0 - 3 + r, gx = x0 - 3 + c;
                bool ok = (gy >= 0 && gy < HH && gx >= 0 && gx < WW);
                const float* src = ok ? (inb + gy * WW + gx) : inb;
                cpasync4(sb + S_RF + buf * 1520 + (uint32_t)i * 4, src, ok ? 4u : 0u);
            }
        }
    };

    int buf = 0;
    issue_raw(blockIdx.x, 0);
    CP_COMMIT();

    for (int tile = blockIdx.x; tile < NTILES; tile += NCTA) {
        const int b = tile / TPI;
        const int rem = tile - b * TPI;
        const int yp = rem / 7;
        const int xh = rem - yp * 7;
        const int y0 = yp * TY, x0 = xh * TX;

        CP_WAIT0();
        __syncthreads();   // raw[buf] visible; ALL prev-tile MMA A-reads done

        // ---- phase 1: split raw f32 -> packed (hi | lo<<16) ----
        #pragma unroll
        for (int it = 0; it < 2; it++) {
            int i = tid + it * THREADS;
            if (i < RAWN) {
                float v = lds32f(sb + S_RF + buf * 1520 + (uint32_t)i * 4);
                uint32_t hi, lo;
                split_h(v, hi, lo);
                sts32(sb + S_RHL + (uint32_t)i * 4, hi | (lo << 16));
            }
        }

        // prefetch next tile's raw into other buffer
        {
            int nt = tile + NCTA;
            if (nt < NTILES) issue_raw(nt, buf ^ 1);
            CP_COMMIT();
        }
        __syncthreads();   // rawhl ready

        // ---- phase 2: im2col -> A_hi + A_lo from same packed loads ----
        {
            const int m = tid & 127;          // m = dy*32 + x
            const int half = tid >> 7;
            const int dy = m >> 5, x = m & 31;
            const int ky0 = half ? 4 : 0, ky1 = half ? 7 : 4;
            const uint32_t ah = sb + S_AH + (uint32_t)m * 144;
            const uint32_t al = sb + S_AL + (uint32_t)m * 144;
            for (int ky = ky0; ky < ky1; ky++) {
                uint32_t ra = sb + S_RHL + (uint32_t)(((dy + ky) * RAWC + x) * 4);
                uint32_t w0 = lds32(ra + 0),  w1 = lds32(ra + 4);
                uint32_t w2 = lds32(ra + 8),  w3 = lds32(ra + 12);
                uint32_t w4 = lds32(ra + 16), w5 = lds32(ra + 20);
                uint32_t w6 = lds32(ra + 24), w7 = lds32(ra + 28);
                sts128(ah + ky * 16,
                       __byte_perm(w0, w1, 0x5410), __byte_perm(w2, w3, 0x5410),
                       __byte_perm(w4, w5, 0x5410), __byte_perm(w6, w7, 0x5410));
                sts128(al + ky * 16,
                       __byte_perm(w0, w1, 0x7632), __byte_perm(w2, w3, 0x7632),
                       __byte_perm(w4, w5, 0x7632), __byte_perm(w6, w7, 0x7632));
            }
        }
        __syncthreads();   // A ready

        // ---- phase 3: 2-pass warp MMA (B frags resident) ----
        float acc[32];
        #pragma unroll
        for (int i = 0; i < 32; i++) acc[i] = 0.0f;

        #pragma unroll
        for (int p = 0; p < 2; p++) {
            const uint32_t Ab = sb + (p ? S_AL : S_AH) + aoff;
            #pragma unroll
            for (int k = 0; k < 4; k++) {
                uint32_t a0[4], a1[4];
                LDSM4(a0, Ab + k * 32);            // m-tile 0
                LDSM4(a1, Ab + 2304 + k * 32);     // m-tile 1
                MMA16816(acc + 0,  a0, bf[k][0], bf[k][1]);
                MMA16816(acc + 4,  a0, bf[k][2], bf[k][3]);
                MMA16816(acc + 8,  a0, bf[k][4], bf[k][5]);
                MMA16816(acc + 12, a0, bf[k][6], bf[k][7]);
                MMA16816(acc + 16, a1, bf[k][0], bf[k][1]);
                MMA16816(acc + 20, a1, bf[k][2], bf[k][3]);
                MMA16816(acc + 24, a1, bf[k][4], bf[k][5]);
                MMA16816(acc + 28, a1, bf[k][6], bf[k][7]);
            }
        }

        // ---- phase 4: direct register -> gmem stores ----
        // C fragment: lane (tg=lane&3, gp=lane>>2); element (n, m):
        //   n = wn*32 + in_*8 + 2*tg (+1),  m = wm*32 + im*16 + gp (+8)
        // m stays inside dy == wm; x = im*16 + gp (+8).
        // One STG.32 covers 4 filter-rows x 8 consecutive x = 4 full 32B sectors.
        {
            const int tg = lane & 3, gp = lane >> 2;
            float* ob = out + (size_t)b * (NF * HhW)
                            + (size_t)(y0 + wm) * WW + x0;
            #pragma unroll
            for (int in_ = 0; in_ < 4; in_++) {
                int n0 = wn * 32 + in_ * 8 + 2 * tg;
                float* r0 = ob + (size_t)n0 * HhW;
                float* r1 = r0 + HhW;
                #pragma unroll
                for (int im = 0; im < 2; im++) {
                    const float* a = &acc[(im * 4 + in_) * 4];
                    int xo = im * 16 + gp;
                    r0[xo]     = a[0];
                    r1[xo]     = a[1];
                    r0[xo + 8] = a[2];
                    r1[xo + 8] = a[3];
                }
            }
        }
        buf ^= 1;
        // loop-top sync orders this tile's A reads before next tile's A writes
    }
}

extern "C" void kernel_launch(void* const* d_in, const int* in_sizes, int n_in,
                              void* d_out, int out_size) {
    const float* x = (const float*)d_in[0];   // (32,1,224,224) f32
    const float* k = (const float*)d_in[1];   // (64,7,7) f32
    float* out = (float*)d_out;               // (32,64,224,224) f32

    cudaFuncSetAttribute(conv7x7_mma5_kernel,
                         cudaFuncAttributeMaxDynamicSharedMemorySize, S_TOT);
    conv7x7_mma5_kernel<<<NCTA, THREADS, S_TOT>>>(x, k, out);
}

// round 13
// speedup vs baseline: 1.3240x; 1.2343x over previous
#include <cuda_runtime.h>
#include <cuda_fp16.h>
#include <cstdint>

// Conv 7x7 C=1 implicit GEMM via mma.sync (legacy HMMA; tcgen05 rejected by
// family-level compute_103 target). R13: SINGLE-pass fp16 (A and B both RN
// fp16; measured 2-pass weight-only error was 1.8e-4, input RN adds an
// independent equal term -> ~2.5-3.5e-4, 3x margin under the 1e-3 gate).
// Tile = 4 rows x 32 px (M=128) x 64 filters, K=64 (k=ky*8+kx).
// Inline f32->fp16 im2col (no staging pass), direct register->gmem epilogue,
// 2 syncs/tile, B fragments register-resident, cp.async double-buffered.

#define HH 224
#define WW 224
#define HhW (HH * WW)
#define NB 32
#define NF 64
#define THREADS 256
#define NCTA 296                    // 2 * 148, persistent
#define TY 4
#define TX 32
#define TPI 392                     // 56 * 7 tiles per image
#define NTILES (NB * TPI)           // 12544
#define RAWR 10
#define RAWC 38
#define RAWN (RAWR * RAWC)          // 380

// SMEM layout (bytes). A rows: 72 halves = 144B stride.
#define S_AH 0                      // 128 x 144 = 18432
#define S_B  18432                  // 64 x 144 = 9216 -> 27648
#define S_RF 27648                  // raw f32, 2 x 1520 -> 30688
#define S_TOT 30720                 // + zero pad (covers 1-word overread)

__device__ __forceinline__ uint32_t smem_u32(const void* p) {
    uint32_t a;
    asm("{ .reg .u64 t; cvta.to.shared.u64 t, %1; cvt.u32.u64 %0, t; }" : "=r"(a) : "l"(p));
    return a;
}
__device__ __forceinline__ void sts16(uint32_t a, uint32_t v) {
    asm volatile("st.shared.u16 [%0], %1;" :: "r"(a), "r"(v) : "memory");
}
__device__ __forceinline__ float lds32f(uint32_t a) {
    float v;
    asm volatile("ld.shared.f32 %0, [%1];" : "=f"(v) : "r"(a));
    return v;
}
__device__ __forceinline__ void sts128(uint32_t a, uint32_t r0, uint32_t r1,
                                       uint32_t r2, uint32_t r3) {
    asm volatile("st.shared.v4.b32 [%0], {%1, %2, %3, %4};"
                 :: "r"(a), "r"(r0), "r"(r1), "r"(r2), "r"(r3) : "memory");
}
__device__ __forceinline__ void cpasync4(uint32_t dst, const void* src, uint32_t sz) {
    asm volatile("cp.async.ca.shared.global [%0], [%1], 4, %2;"
                 :: "r"(dst), "l"(src), "r"(sz) : "memory");
}
#define CP_COMMIT() asm volatile("cp.async.commit_group;" ::: "memory")
#define CP_WAIT0()  asm volatile("cp.async.wait_group 0;" ::: "memory")

#define LDSM4(r, addr) \
    asm volatile("ldmatrix.sync.aligned.m8n8.x4.shared.b16 {%0,%1,%2,%3}, [%4];" \
        : "=r"((r)[0]), "=r"((r)[1]), "=r"((r)[2]), "=r"((r)[3]) : "r"(addr))

#define MMA16816(c, a, bb0, bb1) \
    asm volatile("mma.sync.aligned.m16n8k16.row.col.f32.f16.f16.f32 " \
        "{%0,%1,%2,%3}, {%4,%5,%6,%7}, {%8,%9}, {%0,%1,%2,%3};" \
        : "+f"((c)[0]), "+f"((c)[1]), "+f"((c)[2]), "+f"((c)[3]) \
        : "r"((a)[0]), "r"((a)[1]), "r"((a)[2]), "r"((a)[3]), "r"(bb0), "r"(bb1))

__device__ __forceinline__ uint32_t f22h(float a, float b) {
    __half2 h = __floats2half2_rn(a, b);     // low = a, high = b
    return *reinterpret_cast<uint32_t*>(&h);
}

__global__ void __launch_bounds__(THREADS, 2)
conv7x7_mma6_kernel(const float* __restrict__ in,
                    const float* __restrict__ wk,
                    float* __restrict__ out) {
    extern __shared__ char smem[];
    const uint32_t sb = smem_u32(smem);
    const int tid = threadIdx.x;
    const int lane = tid & 31;
    const int wid = tid >> 5;

    // ---- one-time init: zero EVERYTHING (A pad cols, B pad, raw, overread pad) ----
    for (int i = tid * 16; i < S_TOT; i += THREADS * 16)
        sts128(sb + i, 0u, 0u, 0u, 0u);
    __syncthreads();

    // ---- weights -> B fp16 (RN), [f][k=ky*8+kx], row stride 144B ----
    for (int i = tid; i < NF * 49; i += THREADS) {
        int f = i / 49, q = i - f * 49;
        int ky = q / 7, kx = q - ky * 7;
        uint32_t h = (uint32_t)__half_as_ushort(__float2half(wk[i]));
        sts16(sb + S_B + (uint32_t)(f * 144 + (ky * 8 + kx) * 2), h);
    }
    __syncthreads();

    // ---- per-warp ldmatrix lane offsets ----
    const int wm = wid & 3;          // m-tile (4) == dy of this warp's pixels
    const int wn = wid >> 2;         // n-tile (2)
    const uint32_t aoff = (uint32_t)((wm * 32 + (lane & 15)) * 144 + (lane >> 4) * 16);
    const uint32_t boff = (uint32_t)((wn * 32 + (lane & 7) + ((lane >> 4) & 1) * 8) * 144
                                     + ((lane >> 3) & 1) * 16);

    // ---- B fragments: register-resident for the whole kernel ----
    uint32_t bf[4][8];
    #pragma unroll
    for (int k = 0; k < 4; k++) {
        LDSM4(&bf[k][0], sb + S_B + boff + k * 32);          // n-tiles 0,1
        LDSM4(&bf[k][4], sb + S_B + boff + 2304 + k * 32);   // n-tiles 2,3
    }

    // ---- raw issue helper (cp.async f32, zfill OOB) ----
    auto issue_raw = [&](int tile, int buf) {
        const int b = tile / TPI;
        const int rem = tile - b * TPI;
        const int yp = rem / 7;
        const int xh = rem - yp * 7;
        const int y0 = yp * TY, x0 = xh * TX;
        const float* inb = in + (size_t)b * HhW;
        #pragma unroll
        for (int it = 0; it < 2; it++) {
            int i = tid + it * THREADS;
            if (i < RAWN) {
                int r = i / RAWC, c = i - r * RAWC;
                int gy = y0 - 3 + r, gx = x0 - 3 + c;
                bool ok = (gy >= 0 && gy < HH && gx >= 0 && gx < WW);
                const float* src = ok ? (inb + gy * WW + gx) : inb;
                cpasync4(sb + S_RF + buf * 1520 + (uint32_t)i * 4, src, ok ? 4u : 0u);
            }
        }
    };

    int buf = 0;
    issue_raw(blockIdx.x, 0);
    CP_COMMIT();

    for (int tile = blockIdx.x; tile < NTILES; tile += NCTA) {
        const int b = tile / TPI;
        const int rem = tile - b * TPI;
        const int yp = rem / 7;
        const int xh = rem - yp * 7;
        const int y0 = yp * TY, x0 = xh * TX;

        CP_WAIT0();
        __syncthreads();   // raw[buf] visible; prev tile's A reads done

        // prefetch next tile's raw into other buffer (overlaps im2col + MMA)
        {
            int nt = tile + NCTA;
            if (nt < NTILES) issue_raw(nt, buf ^ 1);
            CP_COMMIT();
        }

        // ---- phase 1: im2col, inline f32 -> fp16 RN ----
        // thread (m = tid&127, half = tid>>7): half 0 does ky 0..3, half 1 ky 4..6
        {
            const int m = tid & 127;          // m = dy*32 + x
            const int half = tid >> 7;
            const int dy = m >> 5, x = m & 31;
            const int ky0 = half ? 4 : 0, ky1 = half ? 7 : 4;
            const uint32_t ah = sb + S_AH + (uint32_t)m * 144;
            const uint32_t rb = sb + S_RF + (uint32_t)buf * 1520;
            for (int ky = ky0; ky < ky1; ky++) {
                uint32_t ra = rb + (uint32_t)(((dy + ky) * RAWC + x) * 4);
                float f0 = lds32f(ra + 0),  f1 = lds32f(ra + 4);
                float f2 = lds32f(ra + 8),  f3 = lds32f(ra + 12);
                float f4 = lds32f(ra + 16), f5 = lds32f(ra + 20);
                float f6 = lds32f(ra + 24), f7 = lds32f(ra + 28);
                sts128(ah + ky * 16,
                       f22h(f0, f1), f22h(f2, f3),
                       f22h(f4, f5), f22h(f6, f7));
            }
        }
        __syncthreads();   // A ready

        // ---- phase 2: single-pass warp MMA (B frags resident) ----
        float acc[32];
        #pragma unroll
        for (int i = 0; i < 32; i++) acc[i] = 0.0f;

        {
            const uint32_t Ab = sb + S_AH + aoff;
            #pragma unroll
            for (int k = 0; k < 4; k++) {
                uint32_t a0[4], a1[4];
                LDSM4(a0, Ab + k * 32);            // m-tile 0
                LDSM4(a1, Ab + 2304 + k * 32);     // m-tile 1
                MMA16816(acc + 0,  a0, bf[k][0], bf[k][1]);
                MMA16816(acc + 4,  a0, bf[k][2], bf[k][3]);
                MMA16816(acc + 8,  a0, bf[k][4], bf[k][5]);
                MMA16816(acc + 12, a0, bf[k][6], bf[k][7]);
                MMA16816(acc + 16, a1, bf[k][0], bf[k][1]);
                MMA16816(acc + 20, a1, bf[k][2], bf[k][3]);
                MMA16816(acc + 24, a1, bf[k][4], bf[k][5]);
                MMA16816(acc + 28, a1, bf[k][6], bf[k][7]);
            }
        }

        // ---- phase 3: direct register -> gmem stores ----
        // lane (tg=lane&3, gp=lane>>2): element (n, m):
        //   n = wn*32 + in_*8 + 2*tg (+1),  x = im*16 + gp (+8), dy = wm
        {
            const int tg = lane & 3, gp = lane >> 2;
            float* ob = out + (size_t)b * (NF * HhW)
                            + (size_t)(y0 + wm) * WW + x0;
            #pragma unroll
            for (int in_ = 0; in_ < 4; in_++) {
                int n0 = wn * 32 + in_ * 8 + 2 * tg;
                float* r0 = ob + (size_t)n0 * HhW;
                float* r1 = r0 + HhW;
                #pragma unroll
                for (int im = 0; im < 2; im++) {
                    const float* a = &acc[(im * 4 + in_) * 4];
                    int xo = im * 16 + gp;
                    r0[xo]     = a[0];
                    r1[xo]     = a[1];
                    r0[xo + 8] = a[2];
                    r1[xo + 8] = a[3];
                }
            }
        }
        buf ^= 1;
        // loop-top sync orders this tile's A reads before next tile's A writes
    }
}

extern "C" void kernel_launch(void* const* d_in, const int* in_sizes, int n_in,
                              void* d_out, int out_size) {
    const float* x = (const float*)d_in[0];   // (32,1,224,224) f32
    const float* k = (const float*)d_in[1];   // (64,7,7) f32
    float* out = (float*)d_out;               // (32,64,224,224) f32

    cudaFuncSetAttribute(conv7x7_mma6_kernel,
                         cudaFuncAttributeMaxDynamicSharedMemorySize, S_TOT);
    conv7x7_mma6_kernel<<<NCTA, THREADS, S_TOT>>>(x, k, out);
}

// round 15
// speedup vs baseline: 1.5051x; 1.1368x over previous
#include <cuda_runtime.h>
#include <cuda.h>
#include <cuda_fp16.h>
#include <cstdint>
#include <cstring>

// Conv 7x7 C=1 implicit GEMM via mma.sync. R15: TMA bulk-tensor STORE epilogue
// (R14 fix: correct cuda.h typedef name CUtensorMapFloatOOBfill).
// C tile staged in SMEM (SW128-swizzled, conflict-free STS scatter), drained
// SMEM->L2 by the TMA engine (cp.async.bulk.tensor.3d, sm_90 baseline PTX) --
// output stores leave the L1/LSU pipe entirely (was 59% of L1 wavefronts).
// Single-pass fp16 (rel_err 2.8e-4), B frags register-resident, cp.async
// double-buffered input, inline f32->fp16 im2col.

#define HH 224
#define WW 224
#define HhW (HH * WW)
#define NB 32
#define NF 64
#define THREADS 256
#define NCTA 296                    // 2 * 148, persistent
#define TY 4
#define TX 32
#define TPI 392                     // 56 * 7 tiles per image
#define NTILES (NB * TPI)           // 12544
#define RAWR 10
#define RAWC 38
#define RAWN (RAWR * RAWC)          // 380

// SMEM layout (bytes). A rows: 72 halves = 144B stride.
#define S_AH 0                      // 128 x 144 = 18432
#define S_B  18432                  // 64 x 144 = 9216 -> 27648
#define S_RF 27648                  // raw f32, 2 x 1520 -> 30688 (+pad)
#define S_C  30720                  // C tile [dy][n][x] f32 = 32768 (1024-aligned)
#define S_TOT 63488

// TMA swizzle (SW128): bits[6:4] ^= bits[9:7]
#define SWZ(o) ((o) ^ (((o) >> 3) & 0x70))

__device__ __align__(128) unsigned long long g_tmap[16];

struct TMapBits { unsigned long long w[16]; };

__global__ void tmap_setup_kernel(TMapBits m) {
    if (threadIdx.x < 16) g_tmap[threadIdx.x] = m.w[threadIdx.x];
    __syncthreads();
    if (threadIdx.x == 0)
        asm volatile("fence.proxy.tensormap::generic.release.gpu;" ::: "memory");
}

__device__ __forceinline__ uint32_t smem_u32(const void* p) {
    uint32_t a;
    asm("{ .reg .u64 t; cvta.to.shared.u64 t, %1; cvt.u32.u64 %0, t; }" : "=r"(a) : "l"(p));
    return a;
}
__device__ __forceinline__ void sts16(uint32_t a, uint32_t v) {
    asm volatile("st.shared.u16 [%0], %1;" :: "r"(a), "r"(v) : "memory");
}
__device__ __forceinline__ void sts32f(uint32_t a, float v) {
    asm volatile("st.shared.f32 [%0], %1;" :: "r"(a), "f"(v) : "memory");
}
__device__ __forceinline__ float lds32f(uint32_t a) {
    float v;
    asm volatile("ld.shared.f32 %0, [%1];" : "=f"(v) : "r"(a));
    return v;
}
__device__ __forceinline__ void sts128(uint32_t a, uint32_t r0, uint32_t r1,
                                       uint32_t r2, uint32_t r3) {
    asm volatile("st.shared.v4.b32 [%0], {%1, %2, %3, %4};"
                 :: "r"(a), "r"(r0), "r"(r1), "r"(r2), "r"(r3) : "memory");
}
__device__ __forceinline__ void cpasync4(uint32_t dst, const void* src, uint32_t sz) {
    asm volatile("cp.async.ca.shared.global [%0], [%1], 4, %2;"
                 :: "r"(dst), "l"(src), "r"(sz) : "memory");
}
#define CP_COMMIT() asm volatile("cp.async.commit_group;" ::: "memory")
#define CP_WAIT0()  asm volatile("cp.async.wait_group 0;" ::: "memory")

#define LDSM4(r, addr) \
    asm volatile("ldmatrix.sync.aligned.m8n8.x4.shared.b16 {%0,%1,%2,%3}, [%4];" \
        : "=r"((r)[0]), "=r"((r)[1]), "=r"((r)[2]), "=r"((r)[3]) : "r"(addr))

#define MMA16816(c, a, bb0, bb1) \
    asm volatile("mma.sync.aligned.m16n8k16.row.col.f32.f16.f16.f32 " \
        "{%0,%1,%2,%3}, {%4,%5,%6,%7}, {%8,%9}, {%0,%1,%2,%3};" \
        : "+f"((c)[0]), "+f"((c)[1]), "+f"((c)[2]), "+f"((c)[3]) \
        : "r"((a)[0]), "r"((a)[1]), "r"((a)[2]), "r"((a)[3]), "r"(bb0), "r"(bb1))

__device__ __forceinline__ uint32_t f22h(float a, float b) {
    __half2 h = __floats2half2_rn(a, b);     // low = a, high = b
    return *reinterpret_cast<uint32_t*>(&h);
}

__global__ void __launch_bounds__(THREADS, 2)
conv7x7_mma7_kernel(const float* __restrict__ in,
                    const float* __restrict__ wk) {
    extern __shared__ char smem[];
    const uint32_t sb = smem_u32(smem);
    const int tid = threadIdx.x;
    const int lane = tid & 31;
    const int wid = tid >> 5;

    if (tid == 0)
        asm volatile("fence.proxy.tensormap::generic.acquire.gpu [%0], 128;"
                     :: "l"(g_tmap) : "memory");

    // ---- one-time init: zero A + B + raw regions (padding stays zero) ----
    for (int i = tid * 16; i < S_C; i += THREADS * 16)
        sts128(sb + i, 0u, 0u, 0u, 0u);
    __syncthreads();

    // ---- weights -> B fp16 (RN), [f][k=ky*8+kx], row stride 144B ----
    for (int i = tid; i < NF * 49; i += THREADS) {
        int f = i / 49, q = i - f * 49;
        int ky = q / 7, kx = q - ky * 7;
        uint32_t h = (uint32_t)__half_as_ushort(__float2half(wk[i]));
        sts16(sb + S_B + (uint32_t)(f * 144 + (ky * 8 + kx) * 2), h);
    }
    __syncthreads();

    // ---- per-warp ldmatrix lane offsets ----
    const int wm = wid & 3;          // m-tile (4) == dy of this warp's pixels
    const int wn = wid >> 2;         // n-tile (2)
    const uint32_t aoff = (uint32_t)((wm * 32 + (lane & 15)) * 144 + (lane >> 4) * 16);
    const uint32_t boff = (uint32_t)((wn * 32 + (lane & 7) + ((lane >> 4) & 1) * 8) * 144
                                     + ((lane >> 3) & 1) * 16);

    // ---- B fragments: register-resident for the whole kernel ----
    uint32_t bf[4][8];
    #pragma unroll
    for (int k = 0; k < 4; k++) {
        LDSM4(&bf[k][0], sb + S_B + boff + k * 32);          // n-tiles 0,1
        LDSM4(&bf[k][4], sb + S_B + boff + 2304 + k * 32);   // n-tiles 2,3
    }

    // ---- raw issue helper (cp.async f32, zfill OOB) ----
    auto issue_raw = [&](int tile, int buf) {
        const int b = tile / TPI;
        const int rem = tile - b * TPI;
        const int yp = rem / 7;
        const int xh = rem - yp * 7;
        const int y0 = yp * TY, x0 = xh * TX;
        const float* inb = in + (size_t)b * HhW;
        #pragma unroll
        for (int it = 0; it < 2; it++) {
            int i = tid + it * THREADS;
            if (i < RAWN) {
                int r = i / RAWC, c = i - r * RAWC;
                int gy = y0 - 3 + r, gx = x0 - 3 + c;
                bool ok = (gy >= 0 && gy < HH && gx >= 0 && gx < WW);
                const float* src = ok ? (inb + gy * WW + gx) : inb;
                cpasync4(sb + S_RF + buf * 1520 + (uint32_t)i * 4, src, ok ? 4u : 0u);
            }
        }
    };

    int buf = 0;
    issue_raw(blockIdx.x, 0);
    CP_COMMIT();

    for (int tile = blockIdx.x; tile < NTILES; tile += NCTA) {
        const int b = tile / TPI;
        const int rem = tile - b * TPI;
        const int yp = rem / 7;
        const int xh = rem - yp * 7;
        const int y0 = yp * TY, x0 = xh * TX;

        CP_WAIT0();
        if (tid == 0)
            asm volatile("cp.async.bulk.wait_group.read 0;" ::: "memory");
        __syncthreads();   // raw[buf] ready; C drained; prev A reads done

        // prefetch next tile's raw into other buffer (overlaps im2col + MMA)
        {
            int nt = tile + NCTA;
            if (nt < NTILES) issue_raw(nt, buf ^ 1);
            CP_COMMIT();
        }

        // ---- phase 1: im2col, inline f32 -> fp16 RN ----
        {
            const int m = tid & 127;          // m = dy*32 + x
            const int half = tid >> 7;
            const int dy = m >> 5, x = m & 31;
            const int ky0 = half ? 4 : 0, ky1 = half ? 7 : 4;
            const uint32_t ah = sb + S_AH + (uint32_t)m * 144;
            const uint32_t rb = sb + S_RF + (uint32_t)buf * 1520;
            for (int ky = ky0; ky < ky1; ky++) {
                uint32_t ra = rb + (uint32_t)(((dy + ky) * RAWC + x) * 4);
                float f0 = lds32f(ra + 0),  f1 = lds32f(ra + 4);
                float f2 = lds32f(ra + 8),  f3 = lds32f(ra + 12);
                float f4 = lds32f(ra + 16), f5 = lds32f(ra + 20);
                float f6 = lds32f(ra + 24), f7 = lds32f(ra + 28);
                sts128(ah + ky * 16,
                       f22h(f0, f1), f22h(f2, f3),
                       f22h(f4, f5), f22h(f6, f7));
            }
        }
        __syncthreads();   // A ready

        // ---- phase 2: single-pass warp MMA (B frags resident) ----
        float acc[32];
        #pragma unroll
        for (int i = 0; i < 32; i++) acc[i] = 0.0f;

        {
            const uint32_t Ab = sb + S_AH + aoff;
            #pragma unroll
            for (int k = 0; k < 4; k++) {
                uint32_t a0[4], a1[4];
                LDSM4(a0, Ab + k * 32);            // m-tile 0
                LDSM4(a1, Ab + 2304 + k * 32);     // m-tile 1
                MMA16816(acc + 0,  a0, bf[k][0], bf[k][1]);
                MMA16816(acc + 4,  a0, bf[k][2], bf[k][3]);
                MMA16816(acc + 8,  a0, bf[k][4], bf[k][5]);
                MMA16816(acc + 12, a0, bf[k][6], bf[k][7]);
                MMA16816(acc + 16, a1, bf[k][0], bf[k][1]);
                MMA16816(acc + 20, a1, bf[k][2], bf[k][3]);
                MMA16816(acc + 24, a1, bf[k][4], bf[k][5]);
                MMA16816(acc + 28, a1, bf[k][6], bf[k][7]);
            }
        }

        // ---- phase 3: STS C tile, SW128-swizzled [dy][n][x] (conflict-free) ----
        // off = dy*8192 + n*128 + x*4; swizzle granule = x[4:2]^n[2:0]:
        // within each op, tg varies n[2:0] and gp varies x -> 32 distinct banks.
        {
            const int tg = lane & 3, gp = lane >> 2;
            const uint32_t cb = sb + S_C + (uint32_t)(wm * 8192);
            #pragma unroll
            for (int in_ = 0; in_ < 4; in_++) {
                #pragma unroll
                for (int im = 0; im < 2; im++) {
                    const float* a = &acc[(im * 4 + in_) * 4];
                    uint32_t o00 = (uint32_t)((wn * 32 + in_ * 8 + 2 * tg) * 128
                                              + (im * 16 + gp) * 4);
                    sts32f(cb + SWZ(o00), a[0]);            // (n0,   x)
                    sts32f(cb + SWZ(o00 + 128), a[1]);      // (n0+1, x)
                    sts32f(cb + SWZ(o00 + 32), a[2]);       // (n0,   x+8)
                    sts32f(cb + SWZ(o00 + 160), a[3]);      // (n0+1, x+8)
                }
            }
        }
        __syncthreads();   // C complete

        // ---- phase 4: TMA bulk store SMEM -> gmem (engine, bypasses L1) ----
        if (tid == 0) {
            asm volatile("fence.proxy.async.shared::cta;" ::: "memory");
            asm volatile(
                "cp.async.bulk.tensor.3d.global.shared::cta.tile.bulk_group "
                "[%0, {%1, %2, %3}], [%4];"
                :: "l"(g_tmap), "r"(x0), "r"(b * NF), "r"(y0),
                   "r"(sb + S_C) : "memory");
            asm volatile("cp.async.bulk.commit_group;" ::: "memory");
        }
        buf ^= 1;
        // loop-top wait_group.read + barrier protect C and A reuse
    }

    if (tid == 0)
        asm volatile("cp.async.bulk.wait_group 0;" ::: "memory");
}

typedef CUresult (*PFN_tmapEncode)(
    CUtensorMap*, CUtensorMapDataType, cuuint32_t, void*,
    const cuuint64_t*, const cuuint64_t*, const cuuint32_t*, const cuuint32_t*,
    CUtensorMapInterleave, CUtensorMapSwizzle, CUtensorMapL2promotion,
    CUtensorMapFloatOOBfill);

extern "C" void kernel_launch(void* const* d_in, const int* in_sizes, int n_in,
                              void* d_out, int out_size) {
    const float* x = (const float*)d_in[0];   // (32,1,224,224) f32
    const float* k = (const float*)d_in[1];   // (64,7,7) f32

    // ---- build tensor map for out (x, plane=b*64+n, y), box (32, 64, 4) ----
    void* fp = nullptr;
    cudaDriverEntryPointQueryResult qr;
    cudaGetDriverEntryPoint("cuTensorMapEncodeTiled", &fp,
                            cudaEnableDefault, &qr);
    static CUtensorMap tmap;
    cuuint64_t dims[3]    = {224, (cuuint64_t)NB * NF, 224};
    cuuint64_t strides[2] = {(cuuint64_t)HhW * 4, 224 * 4};  // plane, y (bytes)
    cuuint32_t box[3]     = {32, 64, 4};
    cuuint32_t estr[3]    = {1, 1, 1};
    ((PFN_tmapEncode)fp)(&tmap, CU_TENSOR_MAP_DATA_TYPE_FLOAT32, 3, d_out,
                         dims, strides, box, estr,
                         CU_TENSOR_MAP_INTERLEAVE_NONE,
                         CU_TENSOR_MAP_SWIZZLE_128B,
                         CU_TENSOR_MAP_L2_PROMOTION_L2_128B,
                         CU_TENSOR_MAP_FLOAT_OOB_FILL_NONE);

    TMapBits bits;
    memcpy(&bits, &tmap, sizeof(bits));
    tmap_setup_kernel<<<1, 32>>>(bits);

    cudaFuncSetAttribute(conv7x7_mma7_kernel,
                         cudaFuncAttributeMaxDynamicSharedMemorySize, S_TOT);
    conv7x7_mma7_kernel<<<NCTA, THREADS, S_TOT>>>(x, k);
}